// round 2
// baseline (speedup 1.0000x reference)
#include <cuda_runtime.h>
#include <cuda_bf16.h>
#include <cstdint>

// DeChunkLayer collapses to a gather:
//   cum[b,s]   = inclusive cumsum of boundary_mask along s
//   out[b,s,:] = cum>0 ? compressed_states[b, cum-1, :] : 0
// (the EMA is a fixed point: within a segment y == cur, so boundary_prob drops out)

#define B_ 8
#define S_ 4096
#define D_ 1024

// Scratch: row index per (b,s); -1 means "emit zeros".
__device__ int g_rowidx[B_ * S_];

// ---------------------------------------------------------------------------
// Kernel 1: per-batch inclusive scan of the boundary mask (int32 in memory).
// 1 block / batch, 1024 threads, 4 mask ints each.
// ---------------------------------------------------------------------------
__global__ void __launch_bounds__(1024, 1)
cum_kernel(const int* __restrict__ mask, int* __restrict__ rowidx)
{
    const int b = blockIdx.x;
    const int t = threadIdx.x;            // 0..1023
    const int lane = t & 31;
    const int warp = t >> 5;

    // Load 4 consecutive int32 mask values (16B vectorized)
    int4 v = reinterpret_cast<const int4*>(mask + (size_t)b * S_)[t];
    int m0 = (v.x != 0);
    int m1 = (v.y != 0);
    int m2 = (v.z != 0);
    int m3 = (v.w != 0);
    int tot = m0 + m1 + m2 + m3;

    // Warp inclusive scan of per-thread totals
    int incl = tot;
    #pragma unroll
    for (int o = 1; o < 32; o <<= 1) {
        int n = __shfl_up_sync(0xffffffffu, incl, o);
        if (lane >= o) incl += n;
    }

    __shared__ int wsum[32];
    if (lane == 31) wsum[warp] = incl;
    __syncthreads();

    if (warp == 0) {
        int w = wsum[lane];
        #pragma unroll
        for (int o = 1; o < 32; o <<= 1) {
            int n = __shfl_up_sync(0xffffffffu, w, o);
            if (lane >= o) w += n;
        }
        wsum[lane] = w;   // inclusive scan of warp totals
    }
    __syncthreads();

    int base = (warp > 0 ? wsum[warp - 1] : 0) + (incl - tot); // exclusive prefix

    int c0 = base + m0;
    int c1 = c0 + m1;
    int c2 = c1 + m2;
    int c3 = c2 + m3;

    int4 r;
    r.x = c0 - 1;   // == -1 when cum==0
    r.y = c1 - 1;
    r.z = c2 - 1;
    r.w = c3 - 1;
    reinterpret_cast<int4*>(rowidx + (size_t)b * S_)[t] = r;
}

// ---------------------------------------------------------------------------
// Kernel 2: gather rows. One block per (b,s); 256 threads x float4 = 4 KB row.
// ---------------------------------------------------------------------------
__global__ void __launch_bounds__(256)
gather_kernel(const float* __restrict__ cs,
              const int* __restrict__ rowidx,
              float* __restrict__ out)
{
    const int bs = blockIdx.x;                    // 0 .. B*S-1
    const int b  = bs >> 12;                      // /4096
    const int row = rowidx[bs];
    const int t = threadIdx.x;

    float4* o = reinterpret_cast<float4*>(out + (size_t)bs * D_);

    if (row < 0) {
        o[t] = make_float4(0.f, 0.f, 0.f, 0.f);
    } else {
        const float4* src = reinterpret_cast<const float4*>(
            cs + ((size_t)b * S_ + row) * D_);
        o[t] = __ldg(&src[t]);
    }
}

// ---------------------------------------------------------------------------
extern "C" void kernel_launch(void* const* d_in, const int* in_sizes, int n_in,
                              void* d_out, int out_size)
{
    // Identify inputs by element count (robust to metadata ordering):
    //   compressed_states: 8*4096*1024 = 33554432
    //   boundary_prob:     8*4096*2    = 65536
    //   boundary_mask:     8*4096      = 32768
    const float* cs = nullptr;
    const int*   mask = nullptr;
    for (int i = 0; i < n_in; i++) {
        if (in_sizes[i] == B_ * S_ * D_)      cs   = (const float*)d_in[i];
        else if (in_sizes[i] == B_ * S_)      mask = (const int*)d_in[i];
    }
    float* out = (float*)d_out;

    int* rowidx;
    cudaGetSymbolAddress((void**)&rowidx, g_rowidx);

    cum_kernel<<<B_, 1024>>>(mask, rowidx);
    gather_kernel<<<B_ * S_, 256>>>(cs, rowidx, out);
}

// round 4
// speedup vs baseline: 1.2632x; 1.2632x over previous
#include <cuda_runtime.h>
#include <cuda_bf16.h>
#include <cstdint>

// DeChunkLayer collapses to a gather:
//   cum[b,s]   = inclusive cumsum of boundary_mask along s
//   out[b,s,:] = cum>0 ? compressed_states[b, cum-1, :] : 0
// (the EMA is a fixed point: within a segment y == cur, so boundary_prob drops out)

#define B_ 8
#define S_ 4096
#define D_ 1024
#define ROWS_PER_BLK 8

// Scratch: row index per (b,s); -1 means "emit zeros".
__device__ int g_rowidx[B_ * S_];

// ---------------------------------------------------------------------------
// Kernel 1: per-batch inclusive scan of the boundary mask (int32 in memory).
// 1 block / batch, 1024 threads, 4 mask ints each.
// ---------------------------------------------------------------------------
__global__ void __launch_bounds__(1024, 1)
cum_kernel(const int* __restrict__ mask, int* __restrict__ rowidx)
{
    const int b = blockIdx.x;
    const int t = threadIdx.x;            // 0..1023
    const int lane = t & 31;
    const int warp = t >> 5;

    int4 v = reinterpret_cast<const int4*>(mask + (size_t)b * S_)[t];
    int m0 = (v.x != 0);
    int m1 = (v.y != 0);
    int m2 = (v.z != 0);
    int m3 = (v.w != 0);
    int tot = m0 + m1 + m2 + m3;

    int incl = tot;
    #pragma unroll
    for (int o = 1; o < 32; o <<= 1) {
        int n = __shfl_up_sync(0xffffffffu, incl, o);
        if (lane >= o) incl += n;
    }

    __shared__ int wsum[32];
    if (lane == 31) wsum[warp] = incl;
    __syncthreads();

    if (warp == 0) {
        int w = wsum[lane];
        #pragma unroll
        for (int o = 1; o < 32; o <<= 1) {
            int n = __shfl_up_sync(0xffffffffu, w, o);
            if (lane >= o) w += n;
        }
        wsum[lane] = w;
    }
    __syncthreads();

    int base = (warp > 0 ? wsum[warp - 1] : 0) + (incl - tot);

    int c0 = base + m0;
    int c1 = c0 + m1;
    int c2 = c1 + m2;
    int c3 = c2 + m3;

    int4 r;
    r.x = c0 - 1;
    r.y = c1 - 1;
    r.z = c2 - 1;
    r.w = c3 - 1;
    reinterpret_cast<int4*>(rowidx + (size_t)b * S_)[t] = r;
}

// ---------------------------------------------------------------------------
// Kernel 2: gather. Each block copies ROWS_PER_BLK consecutive output rows.
// 256 threads; thread t handles float4 column t of every row -> 8 independent
// in-flight loads per thread (MLP=8).
// ---------------------------------------------------------------------------
__global__ void __launch_bounds__(256)
gather_kernel(const float* __restrict__ cs,
              const int* __restrict__ rowidx,
              float* __restrict__ out)
{
    const int base = blockIdx.x * ROWS_PER_BLK;   // first (b*S+s) of this block
    const int b    = base >> 12;                  // S_=4096 rows per batch; base%8==0
    const int t    = threadIdx.x;                 // 0..255 -> float4 column

    __shared__ int rows[ROWS_PER_BLK];
    if (t < ROWS_PER_BLK) rows[t] = rowidx[base + t];
    __syncthreads();

    const float4* cs4 = reinterpret_cast<const float4*>(cs) + (size_t)b * (S_ * 256);
    float4* o4 = reinterpret_cast<float4*>(out) + (size_t)base * 256 + t;

    float4 v[ROWS_PER_BLK];
    #pragma unroll
    for (int r = 0; r < ROWS_PER_BLK; r++) {
        int row = rows[r];
        v[r] = (row < 0) ? make_float4(0.f, 0.f, 0.f, 0.f)
                         : __ldg(cs4 + (size_t)row * 256 + t);
    }
    #pragma unroll
    for (int r = 0; r < ROWS_PER_BLK; r++) {
        o4[r * 256] = v[r];
    }
}

// ---------------------------------------------------------------------------
extern "C" void kernel_launch(void* const* d_in, const int* in_sizes, int n_in,
                              void* d_out, int out_size)
{
    const float* cs = nullptr;
    const int*   mask = nullptr;
    for (int i = 0; i < n_in; i++) {
        if (in_sizes[i] == B_ * S_ * D_)      cs   = (const float*)d_in[i];
        else if (in_sizes[i] == B_ * S_)      mask = (const int*)d_in[i];
    }
    float* out = (float*)d_out;

    int* rowidx;
    cudaGetSymbolAddress((void**)&rowidx, g_rowidx);

    cum_kernel<<<B_, 1024>>>(mask, rowidx);
    gather_kernel<<<(B_ * S_) / ROWS_PER_BLK, 256>>>(cs, rowidx, out);
}

// round 5
// speedup vs baseline: 1.2832x; 1.0159x over previous
#include <cuda_runtime.h>
#include <cuda_bf16.h>
#include <cstdint>

// DeChunkLayer collapses to a gather:
//   cum[b,s]   = inclusive cumsum of boundary_mask along s
//   out[b,s,:] = cum>0 ? compressed_states[b, cum-1, :] : 0
// Fully fused: each block recomputes its prefix count from the (L2-resident)
// mask, then gathers 16 output rows with MLP=8 float4 loads per thread.

#define B_ 8
#define S_ 4096
#define D_ 1024
#define ROWS_PER_BLK 16

__global__ void __launch_bounds__(256)
fused_kernel(const float* __restrict__ cs,
             const int* __restrict__ mask,
             float* __restrict__ out)
{
    const int base = blockIdx.x * ROWS_PER_BLK;   // global (b*S+s) of first row
    const int b    = base >> 12;                  // / S_
    const int s0   = base & (S_ - 1);             // row within batch (mult of 16)
    const int t    = threadIdx.x;
    const int lane = t & 31;
    const int warp = t >> 5;

    const int* mrow = mask + (size_t)b * S_;

    // ---- 1) count boundaries in [0, s0) --------------------------------
    int cnt = 0;
    const int4* m4 = reinterpret_cast<const int4*>(mrow);
    for (int i = t; i < (s0 >> 2); i += 256) {
        int4 v = __ldg(&m4[i]);
        cnt += (v.x != 0) + (v.y != 0) + (v.z != 0) + (v.w != 0);
    }
    #pragma unroll
    for (int o = 16; o; o >>= 1)
        cnt += __shfl_xor_sync(0xffffffffu, cnt, o);

    __shared__ int ws[8];
    __shared__ int rows[ROWS_PER_BLK];
    if (lane == 0) ws[warp] = cnt;
    __syncthreads();

    // ---- 2) warp 0: total + inclusive scan of this block's 16 mask bits
    if (warp == 0) {
        int v = (lane < 8) ? ws[lane] : 0;
        #pragma unroll
        for (int o = 4; o; o >>= 1)
            v += __shfl_xor_sync(0xffffffffu, v, o);      // lanes 0..7 -> total
        int total = __shfl_sync(0xffffffffu, v, 0);

        int m = (lane < ROWS_PER_BLK) ? (mrow[s0 + lane] != 0) : 0;
        int incl = m;
        #pragma unroll
        for (int o = 1; o < ROWS_PER_BLK; o <<= 1) {
            int n = __shfl_up_sync(0xffffffffu, incl, o);
            if (lane >= o) incl += n;
        }
        if (lane < ROWS_PER_BLK)
            rows[lane] = total + incl - 1;                // -1 => emit zeros
    }
    __syncthreads();

    // ---- 3) gather 16 rows, two MLP=8 batches --------------------------
    const float4* cs4 = reinterpret_cast<const float4*>(cs) + (size_t)b * (S_ * 256);
    float4* o4 = reinterpret_cast<float4*>(out) + (size_t)base * 256 + t;

    #pragma unroll
    for (int half = 0; half < 2; half++) {
        float4 v[8];
        #pragma unroll
        for (int r = 0; r < 8; r++) {
            int row = rows[half * 8 + r];
            v[r] = (row < 0) ? make_float4(0.f, 0.f, 0.f, 0.f)
                             : __ldg(cs4 + (size_t)row * 256 + t);
        }
        #pragma unroll
        for (int r = 0; r < 8; r++)
            o4[(size_t)(half * 8 + r) * 256] = v[r];
    }
}

// ---------------------------------------------------------------------------
extern "C" void kernel_launch(void* const* d_in, const int* in_sizes, int n_in,
                              void* d_out, int out_size)
{
    const float* cs = nullptr;
    const int*   mask = nullptr;
    for (int i = 0; i < n_in; i++) {
        if (in_sizes[i] == B_ * S_ * D_)      cs   = (const float*)d_in[i];
        else if (in_sizes[i] == B_ * S_)      mask = (const int*)d_in[i];
    }
    float* out = (float*)d_out;

    fused_kernel<<<(B_ * S_) / ROWS_PER_BLK, 256>>>(cs, mask, out);
}